// round 17
// baseline (speedup 1.0000x reference)
#include <cuda_runtime.h>
#include <cuda_fp16.h>
#include <cstdint>

#define TT 2048
#define BB 64
#define HH 128
#define GG 384
#define MTOT (BB * TT)   // 131072
#define NC 16            // pipeline chunks
#define TCH (TT / NC)    // 128 steps per chunk
// fp16 gemm smem: AsH[64][68] + AsL[64][68] + Bs[64][136] (u32)
#define SMEMB ((64 * 68 * 2 + 64 * 136) * 4)

// Scratch (device globals: no runtime allocation allowed)
__device__ float g_gx[(size_t)3 * MTOT * GG];       // per-layer pre-activations
__device__ float g_h[3 * BB * HH];                  // chunk-boundary hidden
__device__ unsigned short g_xhi[(size_t)MTOT * HH]; // X fp16 hi
__device__ unsigned short g_xlo[(size_t)MTOT * HH]; // X fp16 lo (residual)
__device__ unsigned short g_bhi[(size_t)3 * MTOT * HH]; // layer outputs hi
__device__ unsigned short g_blo[(size_t)3 * MTOT * HH]; // layer outputs lo
__device__ uint32_t g_wk16[64 * GG];                // Wk fp16 k-pairs [kp][n]
__device__ uint32_t g_wo16[64 * HH];                // Wo fp16 k-pairs [kp][n]
__device__ uint32_t g_wr16[64 * GG];                // Wr fp16 k-pairs [kp][n]

// ---------- helpers ----------
__device__ __forceinline__ float sigm(float x) {           // exact (out layer)
    return 1.0f / (1.0f + __expf(-x));
}
__device__ __forceinline__ float tanh_hw(float x) {        // MUFU.TANH
    float y;
    asm("tanh.approx.f32 %0, %1;" : "=f"(y) : "f"(x));
    return y;
}
__device__ __forceinline__ float sigm_hw(float x) {
    return fmaf(tanh_hw(0.5f * x), 0.5f, 0.5f);
}
__device__ __forceinline__ void mma_f16(float* c, uint32_t a0, uint32_t a1,
                                        uint32_t a2, uint32_t a3,
                                        uint32_t b0, uint32_t b1) {
    asm volatile(
        "mma.sync.aligned.m16n8k16.row.col.f32.f16.f16.f32 "
        "{%0,%1,%2,%3}, {%4,%5,%6,%7}, {%8,%9}, {%0,%1,%2,%3};"
        : "+f"(c[0]), "+f"(c[1]), "+f"(c[2]), "+f"(c[3])
        : "r"(a0), "r"(a1), "r"(a2), "r"(a3), "r"(b0), "r"(b1));
}
__device__ __forceinline__ uint32_t packh(float lo, float hi) {
    unsigned short l = __half_as_ushort(__float2half_rn(lo));
    unsigned short h = __half_as_ushort(__float2half_rn(hi));
    return (uint32_t)l | ((uint32_t)h << 16);
}

// ============================================================================
// Weight pack: Wk/Wo/Wr -> fp16 k-pairs [kp][n] (lo half = even k).
// ============================================================================
__global__ void __launch_bounds__(256) pack_w(const float* __restrict__ wk,
                                              const float* __restrict__ wo,
                                              const float* __restrict__ wr) {
    int i = blockIdx.x * 256 + threadIdx.x;
    if (i < 64 * GG) {
        int kp = i / GG, n = i % GG;
        g_wk16[kp * GG + n] = packh(wk[(2 * kp) * GG + n],
                                    wk[(2 * kp + 1) * GG + n]);
    } else if (i < 64 * GG + 64 * HH) {
        int j = i - 64 * GG;
        int kp = j / HH, n = j % HH;
        g_wo16[kp * HH + n] = packh(wo[(2 * kp) * HH + n],
                                    wo[(2 * kp + 1) * HH + n]);
    } else {
        int j = i - 64 * GG - 64 * HH;
        if (j < 64 * GG) {
            int kp = j / GG, n = j % GG;
            g_wr16[kp * GG + n] = packh(wr[(2 * kp) * GG + n],
                                        wr[(2 * kp + 1) * GG + n]);
        }
    }
}

// ============================================================================
// X split: fp32 -> fp16 hi + fp16 lo (residual), packed as u32 k-pairs.
// ============================================================================
__global__ void __launch_bounds__(256) split_x(const float* __restrict__ X) {
    size_t i = (size_t)blockIdx.x * 256 + threadIdx.x;
    if (i >= (size_t)MTOT * 64) return;
    float2 v = ((const float2*)X)[i];
    __half hx = __float2half_rn(v.x);
    __half hy = __float2half_rn(v.y);
    float rx = v.x - __half2float(hx);
    float ry = v.y - __half2float(hy);
    ((uint32_t*)g_xhi)[i] = (uint32_t)__half_as_ushort(hx) |
                            ((uint32_t)__half_as_ushort(hy) << 16);
    ((uint32_t*)g_xlo)[i] = packh(rx, ry);
}

// ============================================================================
// TENSOR-CORE batched GRU scan: 16 batch rows per CTA, 256 threads, grid 4.
// Per step: [16x128](h, fp16 hi+lo) @ [128x384](Wr fp16, register-resident)
// via mma.m16n8k16 (fragment math cloned from the verified gemm_fp16), D to
// smem, gates on all 256 threads (8 h-updates each, MUFU.TANH), h repacked
// to fp16 hi+lo smem. 2 barriers/step.
// ============================================================================
__global__ void __launch_bounds__(256, 1) gru_scan16(
    const float* __restrict__ gx, const uint32_t* __restrict__ wr16,
    const float* __restrict__ brec, unsigned short* __restrict__ outhi,
    unsigned short* __restrict__ outlo, float* __restrict__ hstate, int t0)
{
    __shared__ __align__(16) uint32_t hsH[16 * 68];   // h fp16-hi k-pairs
    __shared__ __align__(16) uint32_t hsL[16 * 68];   // h fp16-lo k-pairs
    __shared__ __align__(16) float sg[16 * 392];      // mma D (pre-gates)

    const int tid = threadIdx.x;
    const int b0 = blockIdx.x * 16;
    const int lane = tid & 31, w = tid >> 5;
    const int g = lane >> 2, t4 = lane & 3;

    // B fragments (Wr), register-resident: 6 n8-tiles x 8 k16-steps x 2.
    uint32_t Bf[6][8][2];
#pragma unroll
    for (int s = 0; s < 6; ++s)
#pragma unroll
        for (int ks = 0; ks < 8; ++ks) {
            const int bc = w * 48 + s * 8 + g;
            Bf[s][ks][0] = wr16[(ks * 8 + t4) * GG + bc];
            Bf[s][ks][1] = wr16[(ks * 8 + t4 + 4) * GG + bc];
        }

    // Gate-phase mapping: thread -> (row, 8 consecutive h-columns).
    const int row = tid >> 4;
    const int cc0 = (tid & 15) * 8;
    float bz[8], br_[8], bh_[8];
#pragma unroll
    for (int j = 0; j < 8; ++j) {
        bz[j] = brec[cc0 + j];
        br_[j] = brec[128 + cc0 + j];
        bh_[j] = brec[256 + cc0 + j];
    }
    float hprev[8];
#pragma unroll
    for (int j = 0; j < 8; ++j)
        hprev[j] = (t0 == 0) ? 0.0f : hstate[(b0 + row) * HH + cc0 + j];

    // Write initial h to smem (fp16 hi+lo k-pairs).
    {
        uint32_t hh[4], hl[4];
#pragma unroll
        for (int p = 0; p < 4; ++p) {
            float v0 = hprev[2 * p], v1 = hprev[2 * p + 1];
            __half h0 = __float2half_rn(v0), h1 = __float2half_rn(v1);
            hh[p] = (uint32_t)__half_as_ushort(h0) |
                    ((uint32_t)__half_as_ushort(h1) << 16);
            hl[p] = packh(v0 - __half2float(h0), v1 - __half2float(h1));
        }
        *(uint4*)&hsH[row * 68 + cc0 / 2] = make_uint4(hh[0], hh[1], hh[2], hh[3]);
        *(uint4*)&hsL[row * 68 + cc0 / 2] = make_uint4(hl[0], hl[1], hl[2], hl[3]);
    }
    __syncthreads();

    const float* gxr = gx + (size_t)(b0 + row) * TT * GG;
    unsigned short* ohp = outhi + (size_t)(b0 + row) * TT * HH;
    unsigned short* olp = outlo + (size_t)(b0 + row) * TT * HH;

    const int tend = t0 + TCH;
    for (int t = t0; t < tend; ++t) {
        // Prefetch gx for this step (consumed after bar1; mma hides latency).
        const float* gxt = gxr + (size_t)t * GG;
        float4 gz0 = *(const float4*)(gxt + cc0);
        float4 gz1 = *(const float4*)(gxt + cc0 + 4);
        float4 gr0 = *(const float4*)(gxt + 128 + cc0);
        float4 gr1 = *(const float4*)(gxt + 128 + cc0 + 4);
        float4 gh0 = *(const float4*)(gxt + 256 + cc0);
        float4 gh1 = *(const float4*)(gxt + 256 + cc0 + 4);

        // MMA phase: D = h_hi @ Wr + h_lo @ Wr  (fp32 accum).
        float acc[6][4];
#pragma unroll
        for (int s = 0; s < 6; ++s)
#pragma unroll
            for (int q = 0; q < 4; ++q) acc[s][q] = 0.0f;

#pragma unroll
        for (int ks = 0; ks < 8; ++ks) {
            const int kp0 = ks * 8;
            uint32_t ah0 = hsH[g * 68 + kp0 + t4];
            uint32_t ah1 = hsH[(g + 8) * 68 + kp0 + t4];
            uint32_t ah2 = hsH[g * 68 + kp0 + t4 + 4];
            uint32_t ah3 = hsH[(g + 8) * 68 + kp0 + t4 + 4];
            uint32_t al0 = hsL[g * 68 + kp0 + t4];
            uint32_t al1 = hsL[(g + 8) * 68 + kp0 + t4];
            uint32_t al2 = hsL[g * 68 + kp0 + t4 + 4];
            uint32_t al3 = hsL[(g + 8) * 68 + kp0 + t4 + 4];
#pragma unroll
            for (int s = 0; s < 6; ++s) {
                mma_f16(acc[s], ah0, ah1, ah2, ah3, Bf[s][ks][0], Bf[s][ks][1]);
                mma_f16(acc[s], al0, al1, al2, al3, Bf[s][ks][0], Bf[s][ks][1]);
            }
        }
        // D -> smem (rows g, g+8; cols w*48 + s*8 + 2*t4).
#pragma unroll
        for (int s = 0; s < 6; ++s) {
            const int col = w * 48 + s * 8 + 2 * t4;
            *(float2*)&sg[g * 392 + col] = make_float2(acc[s][0], acc[s][1]);
            *(float2*)&sg[(g + 8) * 392 + col] = make_float2(acc[s][2], acc[s][3]);
        }
        __syncthreads();   // bar1: D visible

        // Gate phase: 8 h-updates per thread.
        float4 az0 = *(const float4*)&sg[row * 392 + cc0];
        float4 az1 = *(const float4*)&sg[row * 392 + cc0 + 4];
        float4 ar0 = *(const float4*)&sg[row * 392 + 128 + cc0];
        float4 ar1 = *(const float4*)&sg[row * 392 + 128 + cc0 + 4];
        float4 ah0v = *(const float4*)&sg[row * 392 + 256 + cc0];
        float4 ah1v = *(const float4*)&sg[row * 392 + 256 + cc0 + 4];

        const float* azp = (const float*)&az0;   // [0..3] then az1
        const float* az1p = (const float*)&az1;
        const float* arp = (const float*)&ar0;
        const float* ar1p = (const float*)&ar1;
        const float* ahp = (const float*)&ah0v;
        const float* ah1p = (const float*)&ah1v;
        const float* gzp = (const float*)&gz0;
        const float* gz1p = (const float*)&gz1;
        const float* grp = (const float*)&gr0;
        const float* gr1p = (const float*)&gr1;
        const float* ghp = (const float*)&gh0;
        const float* gh1p = (const float*)&gh1;

        uint32_t hh[4], hl[4];
#pragma unroll
        for (int j = 0; j < 8; ++j) {
            const float az = (j < 4 ? azp[j] : az1p[j - 4]) +
                             (j < 4 ? gzp[j] : gz1p[j - 4]) + bz[j];
            const float ar = (j < 4 ? arp[j] : ar1p[j - 4]) +
                             (j < 4 ? grp[j] : gr1p[j - 4]) + br_[j];
            const float ah = (j < 4 ? ahp[j] : ah1p[j - 4]) + bh_[j];
            const float gxh = (j < 4 ? ghp[j] : gh1p[j - 4]);
            const float z = sigm_hw(az);
            const float r = sigm_hw(ar);
            const float cand = tanh_hw(gxh + r * ah);
            const float hn = fmaf(z, hprev[j] - cand, cand);
            hprev[j] = hn;
            __half bhh = __float2half_rn(hn);
            const float hif = __half2float(bhh);
            __half bll = __float2half_rn(hn - hif);
            if (j & 1) {
                const int p = j >> 1;
                hh[p] |= (uint32_t)__half_as_ushort(bhh) << 16;
                hl[p] |= (uint32_t)__half_as_ushort(bll) << 16;
            } else {
                const int p = j >> 1;
                hh[p] = (uint32_t)__half_as_ushort(bhh);
                hl[p] = (uint32_t)__half_as_ushort(bll);
            }
        }
        // h -> smem (next step's A operand) + outputs to gmem.
        *(uint4*)&hsH[row * 68 + cc0 / 2] = make_uint4(hh[0], hh[1], hh[2], hh[3]);
        *(uint4*)&hsL[row * 68 + cc0 / 2] = make_uint4(hl[0], hl[1], hl[2], hl[3]);
        *(uint4*)(ohp + (size_t)t * HH + cc0) = make_uint4(hh[0], hh[1], hh[2], hh[3]);
        *(uint4*)(olp + (size_t)t * HH + cc0) = make_uint4(hl[0], hl[1], hl[2], hl[3]);
        __syncthreads();   // bar2: h ready for next step's mma
    }

    // Save chunk-boundary hidden state.
    *(float4*)&hstate[(b0 + row) * HH + cc0] =
        make_float4(hprev[0], hprev[1], hprev[2], hprev[3]);
    *(float4*)&hstate[(b0 + row) * HH + cc0 + 4] =
        make_float4(hprev[4], hprev[5], hprev[6], hprev[7]);
}

// ============================================================================
// 2-term fp16 tensor-core GEMM + bias (+ optional EXACT sigmoid), BN=128.
// TCH=128: two 64-row tiles per batch row per chunk.
// ============================================================================
__global__ void __launch_bounds__(256, 2) gemm_fp16(
    const uint32_t* __restrict__ Ahi, const uint32_t* __restrict__ Alo,
    const uint32_t* __restrict__ Wpk, const float* __restrict__ bias,
    float* __restrict__ C, int N, int do_sig, int t0)
{
    extern __shared__ uint32_t sm[];
    uint32_t* AsH = sm;                 // [64][68]
    uint32_t* AsL = sm + 64 * 68;       // [64][68]
    uint32_t* Bs  = sm + 2 * 64 * 68;   // [64][136]

    const int tid = threadIdx.x;
    const int nb = blockIdx.x;
    const int m0 = (nb >> 1) * TT + t0 + (nb & 1) * 64;
    const int n0 = blockIdx.y * 128;

    const uint4* Ah4 = (const uint4*)(Ahi + (size_t)m0 * 64);
    const uint4* Al4 = (const uint4*)(Alo + (size_t)m0 * 64);
#pragma unroll
    for (int i = 0; i < 4; ++i) {
        int idx = i * 256 + tid;       // 0..1023
        int r = idx >> 4, c4 = idx & 15;
        *(uint4*)(AsH + r * 68 + c4 * 4) = Ah4[idx];
        *(uint4*)(AsL + r * 68 + c4 * 4) = Al4[idx];
    }
    const int N4 = N >> 2;
    const uint4* W4 = (const uint4*)Wpk;
#pragma unroll
    for (int i = 0; i < 8; ++i) {
        int idx = i * 256 + tid;       // 0..2047
        int kp = idx >> 5, c4 = idx & 31;
        *(uint4*)(Bs + kp * 136 + c4 * 4) = W4[(size_t)kp * N4 + (n0 >> 2) + c4];
    }
    __syncthreads();

    const int lane = tid & 31, wid = tid >> 5;
    const int g = lane >> 2, t = lane & 3;
    const int ms = (wid & 3) * 16;
    const int nh = (wid >> 2) * 64;

    float acc[8][4];
#pragma unroll
    for (int s = 0; s < 8; ++s)
#pragma unroll
        for (int q = 0; q < 4; ++q) acc[s][q] = 0.0f;

#pragma unroll
    for (int ks = 0; ks < 8; ++ks) {
        const int kp0 = ks * 8;        // 8 k-pairs = k16 per step
        uint32_t ah0 = AsH[(ms + g) * 68 + kp0 + t];
        uint32_t ah1 = AsH[(ms + g + 8) * 68 + kp0 + t];
        uint32_t ah2 = AsH[(ms + g) * 68 + kp0 + t + 4];
        uint32_t ah3 = AsH[(ms + g + 8) * 68 + kp0 + t + 4];
        uint32_t al0 = AsL[(ms + g) * 68 + kp0 + t];
        uint32_t al1 = AsL[(ms + g + 8) * 68 + kp0 + t];
        uint32_t al2 = AsL[(ms + g) * 68 + kp0 + t + 4];
        uint32_t al3 = AsL[(ms + g + 8) * 68 + kp0 + t + 4];
#pragma unroll
        for (int s = 0; s < 8; ++s) {
            const int bc = nh + s * 8 + g;
            uint32_t b0 = Bs[(kp0 + t) * 136 + bc];
            uint32_t b1 = Bs[(kp0 + t + 4) * 136 + bc];
            mma_f16(acc[s], ah0, ah1, ah2, ah3, b0, b1);
            mma_f16(acc[s], al0, al1, al2, al3, b0, b1);
        }
    }

#pragma unroll
    for (int s = 0; s < 8; ++s) {
        const int col = n0 + nh + s * 8 + 2 * t;
        const float b0v = bias[col], b1v = bias[col + 1];
        float2 v0 = make_float2(acc[s][0] + b0v, acc[s][1] + b1v);
        float2 v1 = make_float2(acc[s][2] + b0v, acc[s][3] + b1v);
        if (do_sig) {
            v0.x = sigm(v0.x); v0.y = sigm(v0.y);
            v1.x = sigm(v1.x); v1.y = sigm(v1.y);
        }
        *(float2*)(C + (size_t)(m0 + ms + g) * N + col) = v0;
        *(float2*)(C + (size_t)(m0 + ms + g + 8) * N + col) = v1;
    }
}

// ============================================================================
// Streams + events (host objects only). Gemm HIGH / scan LOW.
// ============================================================================
struct PipeRes {
    cudaStream_t s[7];   // 0..2 scan (LOW), 3..5 gemm (HIGH), 6 outproj (HIGH)
    cudaEvent_t fork;
    cudaEvent_t eg[3][NC];
    cudaEvent_t es[3][NC];
    cudaEvent_t tail[7];
    PipeRes() {
        int lo, hi;
        cudaDeviceGetStreamPriorityRange(&lo, &hi);
        for (int i = 0; i < 3; ++i)
            cudaStreamCreateWithPriority(&s[i], cudaStreamNonBlocking, lo);
        for (int i = 3; i < 7; ++i)
            cudaStreamCreateWithPriority(&s[i], cudaStreamNonBlocking, hi);
        cudaEventCreateWithFlags(&fork, cudaEventDisableTiming);
        for (int l = 0; l < 3; ++l)
            for (int i = 0; i < NC; ++i) {
                cudaEventCreateWithFlags(&eg[l][i], cudaEventDisableTiming);
                cudaEventCreateWithFlags(&es[l][i], cudaEventDisableTiming);
            }
        for (int i = 0; i < 7; ++i)
            cudaEventCreateWithFlags(&tail[i], cudaEventDisableTiming);
    }
};
static PipeRes P;

extern "C" void kernel_launch(void* const* d_in, const int* in_sizes, int n_in,
                              void* d_out, int out_size)
{
    const float* X    = (const float*)d_in[0];
    const float* Wk   = (const float*)d_in[1];
    const float* Wr   = (const float*)d_in[2];
    const float* bin  = (const float*)d_in[3];
    const float* brec = (const float*)d_in[4];
    const float* Wo   = (const float*)d_in[5];
    const float* bo   = (const float*)d_in[6];
    float* out = (float*)d_out;

    float *gx, *hst;
    unsigned short *xhi, *xlo, *bhi, *blo;
    uint32_t *wk16, *wo16, *wr16;
    cudaGetSymbolAddress((void**)&gx,   g_gx);
    cudaGetSymbolAddress((void**)&hst,  g_h);
    cudaGetSymbolAddress((void**)&xhi,  g_xhi);
    cudaGetSymbolAddress((void**)&xlo,  g_xlo);
    cudaGetSymbolAddress((void**)&bhi,  g_bhi);
    cudaGetSymbolAddress((void**)&blo,  g_blo);
    cudaGetSymbolAddress((void**)&wk16, g_wk16);
    cudaGetSymbolAddress((void**)&wo16, g_wo16);
    cudaGetSymbolAddress((void**)&wr16, g_wr16);

    cudaFuncSetAttribute(gemm_fp16, cudaFuncAttributeMaxDynamicSharedMemorySize,
                         SMEMB);

    // Pre-fork: pack weights, split X (ordered before all worker streams).
    pack_w<<<(2 * 64 * GG + 64 * HH + 255) / 256, 256>>>(Wk, Wo, Wr);
    split_x<<<(int)(((size_t)MTOT * 64 + 255) / 256), 256>>>(X);

    cudaEventRecord(P.fork, 0);
    for (int i = 0; i < 7; ++i) cudaStreamWaitEvent(P.s[i], P.fork, 0);

    const dim3 gg(BB * 2, GG / 128);  // 128 x 3
    const dim3 go(BB * 2, HH / 128);  // 128 x 1

    for (int i = 0; i < NC; ++i) {
        for (int l = 0; l < 3; ++l) {
            const uint32_t* Ah = (l == 0) ? (const uint32_t*)xhi
                : (const uint32_t*)(bhi) + (size_t)(l - 1) * MTOT * 64;
            const uint32_t* Al = (l == 0) ? (const uint32_t*)xlo
                : (const uint32_t*)(blo) + (size_t)(l - 1) * MTOT * 64;
            float* gxl = gx + (size_t)l * MTOT * GG;
            unsigned short* ohl = bhi + (size_t)l * MTOT * HH;
            unsigned short* oll = blo + (size_t)l * MTOT * HH;
            float* hl = hst + (size_t)l * BB * HH;
            cudaStream_t sg = P.s[3 + l];
            cudaStream_t sc = P.s[l];

            if (l > 0) cudaStreamWaitEvent(sg, P.es[l - 1][i], 0);
            if (i >= 2) cudaStreamWaitEvent(sg, P.es[l][i - 2], 0);
            gemm_fp16<<<gg, 256, SMEMB, sg>>>(Ah, Al, wk16, bin, gxl,
                                              GG, 0, i * TCH);
            cudaEventRecord(P.eg[l][i], sg);

            cudaStreamWaitEvent(sc, P.eg[l][i], 0);
            gru_scan16<<<4, 256, 0, sc>>>(gxl, wr16, brec, ohl, oll, hl,
                                          i * TCH);
            cudaEventRecord(P.es[l][i], sc);
        }
        cudaStreamWaitEvent(P.s[6], P.es[2][i], 0);
        gemm_fp16<<<go, 256, SMEMB, P.s[6]>>>(
            (const uint32_t*)bhi + (size_t)2 * MTOT * 64,
            (const uint32_t*)blo + (size_t)2 * MTOT * 64,
            wo16, bo, out, HH, 1, i * TCH);
    }

    for (int i = 0; i < 7; ++i) {
        cudaEventRecord(P.tail[i], P.s[i]);
        cudaStreamWaitEvent(0, P.tail[i], 0);
    }
}